// round 13
// baseline (speedup 1.0000x reference)
#include <cuda_runtime.h>
#include <cuda_bf16.h>
#include <math.h>
#include <stdint.h>

#define BATCH   16384
#define D_INPUT 128
#define HIDDEN  2048
#define OUTP    54
#define NDIM    9
#define NBAS    5
#define NSTEP   100
#define KSPLIT  8

// ---------------- scratch (device globals: allocation forbidden) -------------
// 3K split layouts: A-side rows = [hi | hi | lo], B-side rows = [hi | lo | hi]
__device__ __nv_bfloat16 g_in3[(size_t)BATCH * 3 * D_INPUT];
__device__ __nv_bfloat16 g_w0_3[(size_t)HIDDEN * 3 * D_INPUT];
__device__ __nv_bfloat16 g_w1_3[(size_t)HIDDEN * 3 * HIDDEN];
__device__ __nv_bfloat16 g_h1_3[(size_t)BATCH * 3 * HIDDEN];
__device__ float g_h2[(size_t)BATCH * HIDDEN];
__device__ float g_parp[KSPLIT][(size_t)BATCH * OUTP];   // K-split partials
__device__ float g_par[(size_t)BATCH * OUTP];

// ---------------- helpers -----------------------------------------------------
__device__ __forceinline__ uint32_t smem_u32(const void* p) {
    uint32_t a;
    asm("{ .reg .u64 t; cvta.to.shared.u64 t, %1; cvt.u32.u64 %0, t; }" : "=r"(a) : "l"(p));
    return a;
}
#define SWZ128(off) ((off) ^ (((off) >> 3) & 0x70))

#define CP_ASYNC16(sm, gp) \
    asm volatile("cp.async.cg.shared.global [%0], [%1], 16;" :: "r"(sm), "l"(gp))
#define CP_COMMIT() asm volatile("cp.async.commit_group;" ::: "memory")
#define CP_WAIT(n)  asm volatile("cp.async.wait_group %0;" :: "n"(n) : "memory")

__device__ __forceinline__ void ldm4(uint32_t* r, uint32_t addr) {
    asm volatile("ldmatrix.sync.aligned.m8n8.x4.shared.b16 {%0,%1,%2,%3}, [%4];"
        : "=r"(r[0]), "=r"(r[1]), "=r"(r[2]), "=r"(r[3]) : "r"(addr));
}
__device__ __forceinline__ void mma16816(float* c, const uint32_t* a, const uint32_t* b) {
    asm volatile("mma.sync.aligned.m16n8k16.row.col.f32.bf16.bf16.f32 "
        "{%0,%1,%2,%3}, {%4,%5,%6,%7}, {%8,%9}, {%0,%1,%2,%3};"
        : "+f"(c[0]), "+f"(c[1]), "+f"(c[2]), "+f"(c[3])
        : "r"(a[0]), "r"(a[1]), "r"(a[2]), "r"(a[3]), "r"(b[0]), "r"(b[1]));
}

__device__ __forceinline__ float tanh_acc(float x) {
    float ax = fabsf(x);
    float t;
    if (ax > 9.0f) t = 1.0f;
    else {
        float e = __expf(2.0f * ax);
        t = 1.0f - __fdividef(2.0f, e + 1.0f);
    }
    return copysignf(t, x);
}

__device__ __forceinline__ unsigned long long pack2(float x, float y) {
    unsigned long long r;
    asm("mov.b64 %0, {%1, %2};" : "=l"(r) : "f"(x), "f"(y));
    return r;
}
__device__ __forceinline__ void ffma2(unsigned long long &c, unsigned long long a,
                                      unsigned long long b) {
    asm("fma.rn.f32x2 %0, %1, %2, %0;" : "+l"(c) : "l"(a), "l"(b));
}
__device__ __forceinline__ float lo32(unsigned long long v) { return __uint_as_float((unsigned)v); }
__device__ __forceinline__ float hi32(unsigned long long v) { return __uint_as_float((unsigned)(v >> 32)); }

// ---------------- fp32 -> [hi|hi|lo] / [hi|lo|hi] bf16 split ------------------
template <int ORDER>
__global__ __launch_bounds__(256)
void split3(const float* __restrict__ src, __nv_bfloat16* __restrict__ dst,
            int K, int n4)
{
    int i = blockIdx.x * blockDim.x + threadIdx.x;
    if (i >= n4) return;
    int K4 = K >> 2;
    int row = i / K4, c4 = i - row * K4;
    float4 v = ((const float4*)src)[i];
    float f[4] = {v.x, v.y, v.z, v.w};
    ushort4 h, l;
    unsigned short* hp = &h.x;
    unsigned short* lp = &l.x;
#pragma unroll
    for (int j = 0; j < 4; j++) {
        __nv_bfloat16 hb = __float2bfloat16(f[j]);
        __nv_bfloat16 lb = __float2bfloat16(f[j] - __bfloat162float(hb));
        hp[j] = __bfloat16_as_ushort(hb);
        lp[j] = __bfloat16_as_ushort(lb);
    }
    __nv_bfloat16* base = dst + (size_t)row * 3 * K + c4 * 4;
    ((ushort4*)base)[0] = h;
    if (ORDER == 0) {
        ((ushort4*)(base + K))[0] = h;
        ((ushort4*)(base + 2 * K))[0] = l;
    } else {
        ((ushort4*)(base + K))[0] = l;
        ((ushort4*)(base + 2 * K))[0] = h;
    }
}

// ---------------- persistent mma.sync bf16 GEMM (NT) --------------------------
// C = tanh(A2 @ B2^T + bias). CTA 128x128, BK=64, 256 threads (2x4 warps,
// warp tile 64x32), 3-slot cp.async ring that streams CONTINUOUSLY across
// tiles: the next tile's first stages load during this tile's epilogue.
// MODE 0: write [hi|hi|lo] split rows (3N wide).  MODE 1: write fp32.
#define MMA_STAGE_SZ 32768
#define MMA_B_OFF    16384
#define MMA_SMEM     (3 * MMA_STAGE_SZ)

__device__ __forceinline__ void load_stage_mma(
    uint32_t sb, const __nv_bfloat16* __restrict__ A2,
    const __nv_bfloat16* __restrict__ B2,
    int m0, int n0, int kt, int K2, int tid)
{
#pragma unroll
    for (int i = 0; i < 4; i++) {
        int id = tid + i * 256;
        int row = id >> 3, c16 = id & 7;
        uint32_t sw = SWZ128((uint32_t)(row * 128 + c16 * 16));
        CP_ASYNC16(sb + sw,             A2 + (size_t)(m0 + row) * K2 + kt + c16 * 8);
        CP_ASYNC16(sb + MMA_B_OFF + sw, B2 + (size_t)(n0 + row) * K2 + kt + c16 * 8);
    }
}

template <int MODE>
__global__ __launch_bounds__(256, 2)
void gemm_mma(const __nv_bfloat16* __restrict__ A2, const __nv_bfloat16* __restrict__ B2,
              const float* __restrict__ bias, float* __restrict__ Cf,
              __nv_bfloat16* __restrict__ Csplit, int N, int K2,
              int nTiles, int ntx)
{
    extern __shared__ char smem[];
    uint32_t sbase = smem_u32(smem);
    const int tid = threadIdx.x;
    const int wid = tid >> 5, lane = tid & 31;
    const int wm = wid >> 2, wn = wid & 3;     // 2x4 warp grid
    const int nc = K2 / 64;

    uint32_t roA[4], roB[2];
#pragma unroll
    for (int mt = 0; mt < 4; mt++)
        roA[mt] = (uint32_t)((wm * 64 + mt * 16 + (lane & 15)) * 128 + (lane >> 4) * 16);
#pragma unroll
    for (int p = 0; p < 2; p++)
        roB[p] = (uint32_t)((wn * 32 + p * 16 + (lane & 7) + ((lane >> 4) << 3)) * 128 +
                            ((lane >> 3) & 1) * 16);

    float acc[4][4][4];
#pragma unroll
    for (int a = 0; a < 4; a++)
#pragma unroll
        for (int b = 0; b < 4; b++)
#pragma unroll
            for (int q = 0; q < 4; q++) acc[a][b][q] = 0.0f;

    // lookahead load cursor (tile, kt) — the next chunk to fetch
    int la_tile = blockIdx.x;
    int la_kt = 0;
    // prologue: fill slots 0 and 1
#pragma unroll
    for (int j = 0; j < 2; j++) {
        if (la_tile < nTiles) {
            int lm0 = (la_tile / ntx) * 128, ln0 = (la_tile % ntx) * 128;
            load_stage_mma(sbase + j * MMA_STAGE_SZ, A2, B2, lm0, ln0, la_kt, K2, tid);
            la_kt += 64;
            if (la_kt == K2) { la_kt = 0; la_tile += gridDim.x; }
        }
        CP_COMMIT();
    }

    int slot = 0;   // consumption slot, advances mod 3 per chunk
    for (int tile = blockIdx.x; tile < nTiles; tile += gridDim.x) {
        const int m0 = (tile / ntx) * 128;
        const int n0 = (tile % ntx) * 128;

        for (int c = 0; c < nc; c++) {
            CP_WAIT(1);
            __syncthreads();      // chunk data visible; slot (slot+2)%3 free for reuse

            uint32_t sA = sbase + slot * MMA_STAGE_SZ;
            uint32_t sB = sA + MMA_B_OFF;

            uint32_t af[4][4], bf[2][2][4];
#pragma unroll
            for (int mt = 0; mt < 4; mt++) ldm4(af[mt], sA + SWZ128(roA[mt]));
#pragma unroll
            for (int p = 0; p < 2; p++) ldm4(bf[0][p], sB + SWZ128(roB[p]));

            // issue gmem loads for chunk slot+2 (possibly next tile's stage)
            if (la_tile < nTiles) {
                int lm0 = (la_tile / ntx) * 128, ln0 = (la_tile % ntx) * 128;
                load_stage_mma(sbase + ((slot + 2) % 3) * MMA_STAGE_SZ, A2, B2,
                               lm0, ln0, la_kt, K2, tid);
                la_kt += 64;
                if (la_kt == K2) { la_kt = 0; la_tile += gridDim.x; }
            }
            CP_COMMIT();

#pragma unroll
            for (int ks = 0; ks < 4; ks++) {
                const int cur = ks & 1, nxt = cur ^ 1;
                if (ks < 3) {
#pragma unroll
                    for (int p = 0; p < 2; p++)
                        ldm4(bf[nxt][p], sB + SWZ128(roB[p] + (ks + 1) * 32));
                }
#pragma unroll
                for (int mt = 0; mt < 4; mt++) {
#pragma unroll
                    for (int nt = 0; nt < 4; nt++)
                        mma16816(acc[mt][nt], af[mt], &bf[cur][nt >> 1][(nt & 1) * 2]);
                    if (ks < 3)
                        ldm4(af[mt], sA + SWZ128(roA[mt] + (ks + 1) * 32));
                }
            }
            slot = (slot + 1) % 3;
        }

        // ---- epilogue for this tile (overlaps with in-flight next-tile loads)
        const int mrow = m0 + wm * 64 + (lane >> 2);
        const int nbase = n0 + wn * 32 + 2 * (lane & 3);
#pragma unroll
        for (int mt = 0; mt < 4; mt++) {
#pragma unroll
            for (int nt = 0; nt < 4; nt++) {
                int n = nbase + nt * 8;
                float2 b2 = *(const float2*)(bias + n);
                float v0 = tanh_acc(acc[mt][nt][0] + b2.x);
                float v1 = tanh_acc(acc[mt][nt][1] + b2.y);
                float v2 = tanh_acc(acc[mt][nt][2] + b2.x);
                float v3 = tanh_acc(acc[mt][nt][3] + b2.y);
                int r0 = mrow + mt * 16, r1 = r0 + 8;
                if (MODE == 0) {
#pragma unroll
                    for (int h = 0; h < 2; h++) {
                        float u0 = h ? v2 : v0, u1 = h ? v3 : v1;
                        int r = h ? r1 : r0;
                        __nv_bfloat16 h0 = __float2bfloat16(u0);
                        __nv_bfloat16 h1 = __float2bfloat16(u1);
                        __nv_bfloat16 l0 = __float2bfloat16(u0 - __bfloat162float(h0));
                        __nv_bfloat16 l1 = __float2bfloat16(u1 - __bfloat162float(h1));
                        uint32_t hp = (uint32_t)__bfloat16_as_ushort(h0) |
                                      ((uint32_t)__bfloat16_as_ushort(h1) << 16);
                        uint32_t lp = (uint32_t)__bfloat16_as_ushort(l0) |
                                      ((uint32_t)__bfloat16_as_ushort(l1) << 16);
                        __nv_bfloat16* row = Csplit + (size_t)r * 3 * N + n;
                        *(uint32_t*)row = hp;
                        *(uint32_t*)(row + N) = hp;
                        *(uint32_t*)(row + 2 * N) = lp;
                    }
                } else {
                    *(float2*)(Cf + (size_t)r0 * N + n) = make_float2(v0, v1);
                    *(float2*)(Cf + (size_t)r1 * N + n) = make_float2(v2, v3);
                }
                acc[mt][nt][0] = 0.0f; acc[mt][nt][1] = 0.0f;
                acc[mt][nt][2] = 0.0f; acc[mt][nt][3] = 0.0f;
            }
        }
    }
}

// ---------------- K-split 64x64 FFMA2 GEMM partials for final layer ----------
__global__ __launch_bounds__(256, 4)
void gemm64s(const float* __restrict__ A, const float* __restrict__ Bm,
             float* __restrict__ Cp, int N, int K)
{
    __shared__ __align__(16) float As[16 * 64];
    __shared__ __align__(16) float Bs[16 * 64];

    const int tid = threadIdx.x;
    const int split = blockIdx.x;
    const int kbase = split * (K / KSPLIT);
    const int kend = kbase + K / KSPLIT;
    const int m0 = blockIdx.y * 64;
    const int tr = tid >> 4;
    const int tc = tid & 15;
    const int r = tid >> 2;
    const int c0 = (tid & 3) << 2;

    float* C = Cp + (size_t)split * BATCH * OUTP;

    unsigned long long acc[4][2];
#pragma unroll
    for (int i = 0; i < 4; i++) { acc[i][0] = 0ull; acc[i][1] = 0ull; }

    for (int kt = kbase; kt < kend; kt += 16) {
        float4 va = *(const float4*)(A + (size_t)(m0 + r) * K + kt + c0);
        float4 vb = make_float4(0.f, 0.f, 0.f, 0.f);
        if (r < N) vb = *(const float4*)(Bm + (size_t)r * K + kt + c0);

        __syncthreads();
        As[(c0 + 0) * 64 + r] = va.x; As[(c0 + 1) * 64 + r] = va.y;
        As[(c0 + 2) * 64 + r] = va.z; As[(c0 + 3) * 64 + r] = va.w;
        Bs[(c0 + 0) * 64 + r] = vb.x; Bs[(c0 + 1) * 64 + r] = vb.y;
        Bs[(c0 + 2) * 64 + r] = vb.z; Bs[(c0 + 3) * 64 + r] = vb.w;
        __syncthreads();

#pragma unroll
        for (int k = 0; k < 16; k++) {
            float4 a = *(const float4*)&As[k * 64 + tr * 4];
            ulonglong2 bb = *(const ulonglong2*)&Bs[k * 64 + tc * 4];
            unsigned long long b2[2] = {bb.x, bb.y};
            unsigned long long a2[4];
            a2[0] = pack2(a.x, a.x); a2[1] = pack2(a.y, a.y);
            a2[2] = pack2(a.z, a.z); a2[3] = pack2(a.w, a.w);
#pragma unroll
            for (int i = 0; i < 4; i++) {
                ffma2(acc[i][0], a2[i], b2[0]);
                ffma2(acc[i][1], a2[i], b2[1]);
            }
        }
    }

#pragma unroll
    for (int i = 0; i < 4; i++) {
        int mg = m0 + tr * 4 + i;
#pragma unroll
        for (int j = 0; j < 2; j++) {
            int ng = tc * 4 + (j << 1);
            if (ng < N)     C[(size_t)mg * N + ng]     = lo32(acc[i][j]);
            if (ng + 1 < N) C[(size_t)mg * N + ng + 1] = hi32(acc[i][j]);
        }
    }
}

// fixed-order reduction of K-split partials + bias + *100  (deterministic)
__global__ __launch_bounds__(256)
void reduce_par(const float* __restrict__ Cp, const float* __restrict__ bias,
                float* __restrict__ par, int total)
{
    int i = blockIdx.x * blockDim.x + threadIdx.x;
    if (i >= total) return;
    int j = i % OUTP;
    float s = 0.0f;
#pragma unroll
    for (int p = 0; p < KSPLIT; p++)
        s += Cp[(size_t)p * BATCH * OUTP + i];
    par[i] = (s + bias[j]) * 100.0f;
}

// ---------------- DMP Euler integration --------------------------------------
__global__ __launch_bounds__(256)
void dmp_kernel(const float* __restrict__ input, float* __restrict__ out)
{
    __shared__ float xs[NSTEP];
    __shared__ float coef[NSTEP][NBAS];

    const int tid = threadIdx.x;
    if (tid == 0) {
        float x = 1.0f;
        for (int i = 0; i < NSTEP; i++) { x = x - x * 0.01f; xs[i] = x; }
    }
    __syncthreads();
    if (tid < NSTEP) {
        float x = xs[tid];
        float p[NBAS];
        float s = 0.0f;
#pragma unroll
        for (int n = 0; n < NBAS; n++) {
            double cd = exp(-0.25 * (double)n);
            float Cn = (float)cd;
            float Hn = (float)(11.180339887498949 / cd);
            float d = x - Cn;
            p[n] = __expf(-Hn * d * d);
            s += p[n];
        }
        float inv = x / s;
#pragma unroll
        for (int n = 0; n < NBAS; n++) coef[tid][n] = p[n] * inv;
    }
    __syncthreads();

    int r = blockIdx.x * blockDim.x + tid;
    if (r >= BATCH * NDIM) return;
    int b = r / NDIM;
    int d = r - b * NDIM;

    const float* prm = g_par + (size_t)b * OUTP;
    float goal = prm[d];
    float w[NBAS];
#pragma unroll
    for (int n = 0; n < NBAS; n++) w[n] = prm[NDIM + d * NBAS + n];

    float y = input[(size_t)b * D_INPUT + 7 + d];
    float z = input[(size_t)b * D_INPUT + 22 + d];
    float scale = goal - y;
    float prev = y;
    float* o = out + (size_t)r * 10;

#pragma unroll 1
    for (int kk = 0; kk < 10; kk++) {
#pragma unroll
        for (int i = 0; i < 10; i++) {
            int t = kk * 10 + i;
            float fx = scale * (w[0] * coef[t][0] + w[1] * coef[t][1] +
                                w[2] * coef[t][2] + w[3] * coef[t][3] +
                                w[4] * coef[t][4]);
            float dz = 25.0f * (6.25f * (goal - y) - z) + fx;
            y = y + z * 0.01f;
            z = z + dz * 0.01f;
        }
        o[kk] = y - prev;
        prev = y;
    }
}

// ---------------- launch ------------------------------------------------------
extern "C" void kernel_launch(void* const* d_in, const int* in_sizes, int n_in,
                              void* d_out, int out_size)
{
    const float* input = (const float*)d_in[0];
    const float* W0 = (const float*)d_in[1];
    const float* b0 = (const float*)d_in[2];
    const float* W1 = (const float*)d_in[3];
    const float* b1 = (const float*)d_in[4];
    const float* Wl = (const float*)d_in[5];
    const float* bl = (const float*)d_in[6];
    float* out = (float*)d_out;

    static __nv_bfloat16 *in3, *w0_3, *w1_3, *h1_3;
    static float *h2, *parp, *par;
    static bool init_done = false;
    if (!init_done) {
        cudaGetSymbolAddress((void**)&in3, g_in3);
        cudaGetSymbolAddress((void**)&w0_3, g_w0_3);
        cudaGetSymbolAddress((void**)&w1_3, g_w1_3);
        cudaGetSymbolAddress((void**)&h1_3, g_h1_3);
        cudaGetSymbolAddress((void**)&h2, g_h2);
        cudaGetSymbolAddress((void**)&parp, g_parp);
        cudaGetSymbolAddress((void**)&par, g_par);
        cudaFuncSetAttribute(gemm_mma<0>, cudaFuncAttributeMaxDynamicSharedMemorySize, MMA_SMEM);
        cudaFuncSetAttribute(gemm_mma<1>, cudaFuncAttributeMaxDynamicSharedMemorySize, MMA_SMEM);
        init_done = true;
    }

    dim3 blk(256);
    const int PERSIST = 296;                 // 2 CTAs x 148 SMs
    const int NTX = HIDDEN / 128;            // 16 N-tiles
    const int NT = (BATCH / 128) * NTX;      // 2048 tiles

    // fp32 -> 3K split-bf16 layouts
    split3<0><<<(BATCH * D_INPUT / 4 + 255) / 256, blk>>>(input, in3, D_INPUT, BATCH * D_INPUT / 4);
    split3<1><<<(HIDDEN * D_INPUT / 4 + 255) / 256, blk>>>(W0, w0_3, D_INPUT, HIDDEN * D_INPUT / 4);
    split3<1><<<(HIDDEN * HIDDEN / 4 + 255) / 256, blk>>>(W1, w1_3, HIDDEN, HIDDEN * HIDDEN / 4);

    // layer 0: tanh(input @ W0^T + b0) -> h1 in [hi|hi|lo] layout (K2 = 384)
    gemm_mma<0><<<PERSIST, blk, MMA_SMEM>>>(in3, w0_3, b0, nullptr, h1_3,
                                            HIDDEN, 3 * D_INPUT, NT, NTX);
    // layer 1: tanh(h1 @ W1^T + b1) -> fp32 h2 (K2 = 6144, dominant)
    gemm_mma<1><<<PERSIST, blk, MMA_SMEM>>>(h1_3, w1_3, b1, h2, nullptr,
                                            HIDDEN, 3 * HIDDEN, NT, NTX);
    // final layer, K-split x8 partials, then deterministic reduce
    gemm64s<<<dim3(KSPLIT, BATCH / 64), blk>>>(h2, Wl, parp, OUTP, HIDDEN);
    reduce_par<<<(BATCH * OUTP + 255) / 256, blk>>>(parp, bl, par, BATCH * OUTP);
    // DMP integration + subsample-diff
    dmp_kernel<<<(BATCH * NDIM + 255) / 256, blk>>>(input, out);
}

// round 16
// speedup vs baseline: 1.1856x; 1.1856x over previous
#include <cuda_runtime.h>
#include <cuda_bf16.h>
#include <math.h>
#include <stdint.h>

#define BATCH   16384
#define D_INPUT 128
#define HIDDEN  2048
#define OUTP    54
#define NDIM    9
#define NBAS    5
#define NSTEP   100
#define KSPLIT  8

// ---------------- scratch (device globals: allocation forbidden) -------------
// Interleaved split layout: per 32 orig-K group, 64 bf16 = [hi(32) | lo(32)].
// Row width in bf16 = 2*K_orig. Same layout for A-side and B-side operands.
__device__ __nv_bfloat16 g_in2[(size_t)BATCH * 2 * D_INPUT];
__device__ __nv_bfloat16 g_w0_2[(size_t)HIDDEN * 2 * D_INPUT];
__device__ __nv_bfloat16 g_w1_2[(size_t)HIDDEN * 2 * HIDDEN];
__device__ __nv_bfloat16 g_h1_2[(size_t)BATCH * 2 * HIDDEN];
__device__ float g_h2[(size_t)BATCH * HIDDEN];
__device__ float g_parp[KSPLIT][(size_t)BATCH * OUTP];
__device__ float g_par[(size_t)BATCH * OUTP];

// ---------------- helpers -----------------------------------------------------
__device__ __forceinline__ uint32_t smem_u32(const void* p) {
    uint32_t a;
    asm("{ .reg .u64 t; cvta.to.shared.u64 t, %1; cvt.u32.u64 %0, t; }" : "=r"(a) : "l"(p));
    return a;
}
#define SWZ128(off) ((off) ^ (((off) >> 3) & 0x70))

#define CP_ASYNC16(sm, gp) \
    asm volatile("cp.async.cg.shared.global [%0], [%1], 16;" :: "r"(sm), "l"(gp))
#define CP_COMMIT() asm volatile("cp.async.commit_group;" ::: "memory")
#define CP_WAIT(n)  asm volatile("cp.async.wait_group %0;" :: "n"(n) : "memory")

__device__ __forceinline__ void ldm4(uint32_t* r, uint32_t addr) {
    asm volatile("ldmatrix.sync.aligned.m8n8.x4.shared.b16 {%0,%1,%2,%3}, [%4];"
        : "=r"(r[0]), "=r"(r[1]), "=r"(r[2]), "=r"(r[3]) : "r"(addr));
}
__device__ __forceinline__ void mma16816(float* c, const uint32_t* a, const uint32_t* b) {
    asm volatile("mma.sync.aligned.m16n8k16.row.col.f32.bf16.bf16.f32 "
        "{%0,%1,%2,%3}, {%4,%5,%6,%7}, {%8,%9}, {%0,%1,%2,%3};"
        : "+f"(c[0]), "+f"(c[1]), "+f"(c[2]), "+f"(c[3])
        : "r"(a[0]), "r"(a[1]), "r"(a[2]), "r"(a[3]), "r"(b[0]), "r"(b[1]));
}

__device__ __forceinline__ float tanh_acc(float x) {
    float ax = fabsf(x);
    float t;
    if (ax > 9.0f) t = 1.0f;
    else {
        float e = __expf(2.0f * ax);
        t = 1.0f - __fdividef(2.0f, e + 1.0f);
    }
    return copysignf(t, x);
}

__device__ __forceinline__ unsigned long long pack2(float x, float y) {
    unsigned long long r;
    asm("mov.b64 %0, {%1, %2};" : "=l"(r) : "f"(x), "f"(y));
    return r;
}
__device__ __forceinline__ void ffma2(unsigned long long &c, unsigned long long a,
                                      unsigned long long b) {
    asm("fma.rn.f32x2 %0, %1, %2, %0;" : "+l"(c) : "l"(a), "l"(b));
}
__device__ __forceinline__ float lo32(unsigned long long v) { return __uint_as_float((unsigned)v); }
__device__ __forceinline__ float hi32(unsigned long long v) { return __uint_as_float((unsigned)(v >> 32)); }

// ---------------- fp32 -> interleaved [hi32|lo32] bf16 split ------------------
__global__ __launch_bounds__(256)
void split2(const float* __restrict__ src, __nv_bfloat16* __restrict__ dst,
            int K, int n4)
{
    int i = blockIdx.x * blockDim.x + threadIdx.x;
    if (i >= n4) return;
    int K4 = K >> 2;
    int row = i / K4;
    int k = (i - row * K4) << 2;          // orig column (multiple of 4)
    int g = k >> 5, j = k & 31;
    float4 v = ((const float4*)src)[i];
    float f[4] = {v.x, v.y, v.z, v.w};
    ushort4 h, l;
    unsigned short* hp = &h.x;
    unsigned short* lp = &l.x;
#pragma unroll
    for (int q = 0; q < 4; q++) {
        __nv_bfloat16 hb = __float2bfloat16(f[q]);
        __nv_bfloat16 lb = __float2bfloat16(f[q] - __bfloat162float(hb));
        hp[q] = __bfloat16_as_ushort(hb);
        lp[q] = __bfloat16_as_ushort(lb);
    }
    __nv_bfloat16* base = dst + (size_t)row * 2 * K + g * 64 + j;
    ((ushort4*)base)[0] = h;
    ((ushort4*)(base + 32))[0] = l;
}

// ---------------- mma.sync split-bf16 GEMM (NT) -------------------------------
// C = tanh(A2 @ B2^T + bias) computed as Ah*Bh + Ah*Bl + Al*Bh with register
// fragment reuse (each plane loaded ONCE from smem/gmem).
// CTA 128x128, chunk = 32 orig-K (one [hi|lo] group, 128B/row, SW128),
// 3-slot cp.async ring, 256 threads (2x4 warps, warp tile 64x32).
// MODE 0: write interleaved split rows (2N wide). MODE 1: write fp32.
#define MMA_STAGE_SZ 32768            // A 16KB + B 16KB
#define MMA_B_OFF    16384
#define MMA_SMEM     (3 * MMA_STAGE_SZ)

__device__ __forceinline__ void load_stage_mma(
    uint32_t sb, const __nv_bfloat16* __restrict__ A2,
    const __nv_bfloat16* __restrict__ B2,
    int m0, int n0, int kelem, int K2, int tid)
{
    // each operand: 128 rows x 8 x 16B (one 128B group per row)
#pragma unroll
    for (int i = 0; i < 4; i++) {
        int id = tid + i * 256;
        int row = id >> 3, c16 = id & 7;
        uint32_t sw = SWZ128((uint32_t)(row * 128 + c16 * 16));
        CP_ASYNC16(sb + sw,             A2 + (size_t)(m0 + row) * K2 + kelem + c16 * 8);
        CP_ASYNC16(sb + MMA_B_OFF + sw, B2 + (size_t)(n0 + row) * K2 + kelem + c16 * 8);
    }
}

template <int MODE>
__global__ __launch_bounds__(256, 2)
void gemm_mma(const __nv_bfloat16* __restrict__ A2, const __nv_bfloat16* __restrict__ B2,
              const float* __restrict__ bias, float* __restrict__ Cf,
              __nv_bfloat16* __restrict__ Csplit, int N, int K2)
{
    extern __shared__ char smem[];
    uint32_t sbase = smem_u32(smem);
    const int tid = threadIdx.x;
    const int wid = tid >> 5, lane = tid & 31;
    const int m0 = blockIdx.y * 128;
    const int n0 = blockIdx.x * 128;
    const int wm = wid >> 2, wn = wid & 3;     // 2x4 warp grid
    const int nc = K2 / 64;                    // one 64-elem group per chunk

    // in-tile byte offsets (pre-swizzle); k-step ks adds ks*32, lo adds +64
    uint32_t roA[4], roB[2];
#pragma unroll
    for (int mt = 0; mt < 4; mt++)
        roA[mt] = (uint32_t)((wm * 64 + mt * 16 + (lane & 15)) * 128 + (lane >> 4) * 16);
#pragma unroll
    for (int p = 0; p < 2; p++)
        roB[p] = (uint32_t)((wn * 32 + p * 16 + (lane & 7) + ((lane >> 4) << 3)) * 128 +
                            ((lane >> 3) & 1) * 16);

    float acc[4][4][4];
#pragma unroll
    for (int a = 0; a < 4; a++)
#pragma unroll
        for (int b = 0; b < 4; b++)
#pragma unroll
            for (int q = 0; q < 4; q++) acc[a][b][q] = 0.0f;

    load_stage_mma(sbase, A2, B2, m0, n0, 0, K2, tid);
    CP_COMMIT();
    if (nc > 1) load_stage_mma(sbase + MMA_STAGE_SZ, A2, B2, m0, n0, 64, K2, tid);
    CP_COMMIT();

    for (int c = 0; c < nc; c++) {
        CP_WAIT(1);
        __syncthreads();      // chunk c visible; slot (c+2)%3 free for reuse

        // prefetch chunk c+2
        if (c + 2 < nc)
            load_stage_mma(sbase + ((c + 2) % 3) * MMA_STAGE_SZ, A2, B2,
                           m0, n0, (c + 2) * 64, K2, tid);
        CP_COMMIT();

        uint32_t sA = sbase + (c % 3) * MMA_STAGE_SZ;
        uint32_t sB = sA + MMA_B_OFF;

#pragma unroll
        for (int ks = 0; ks < 2; ks++) {
            uint32_t af[4][4], bh[2][4], bl[2][4];
            // hi planes + B lo plane
#pragma unroll
            for (int mt = 0; mt < 4; mt++)
                ldm4(af[mt], sA + SWZ128(roA[mt] + ks * 32));
#pragma unroll
            for (int p = 0; p < 2; p++) {
                ldm4(bh[p], sB + SWZ128(roB[p] + ks * 32));
                ldm4(bl[p], sB + SWZ128(roB[p] + 64 + ks * 32));
            }
            // hh + hl products (A hi fragments)
#pragma unroll
            for (int mt = 0; mt < 4; mt++) {
#pragma unroll
                for (int nt = 0; nt < 4; nt++)
                    mma16816(acc[mt][nt], af[mt], &bh[nt >> 1][(nt & 1) * 2]);
#pragma unroll
                for (int nt = 0; nt < 4; nt++)
                    mma16816(acc[mt][nt], af[mt], &bl[nt >> 1][(nt & 1) * 2]);
                // af[mt] now dead -> reload with A lo plane
                ldm4(af[mt], sA + SWZ128(roA[mt] + 64 + ks * 32));
            }
            // lh products (A lo fragments)
#pragma unroll
            for (int mt = 0; mt < 4; mt++)
#pragma unroll
                for (int nt = 0; nt < 4; nt++)
                    mma16816(acc[mt][nt], af[mt], &bh[nt >> 1][(nt & 1) * 2]);
        }
    }

    // epilogue
    const int mrow = m0 + wm * 64 + (lane >> 2);
    const int nbase = n0 + wn * 32 + 2 * (lane & 3);
#pragma unroll
    for (int mt = 0; mt < 4; mt++) {
#pragma unroll
        for (int nt = 0; nt < 4; nt++) {
            int n = nbase + nt * 8;
            float2 b2 = *(const float2*)(bias + n);
            float v0 = tanh_acc(acc[mt][nt][0] + b2.x);
            float v1 = tanh_acc(acc[mt][nt][1] + b2.y);
            float v2 = tanh_acc(acc[mt][nt][2] + b2.x);
            float v3 = tanh_acc(acc[mt][nt][3] + b2.y);
            int r0 = mrow + mt * 16, r1 = r0 + 8;
            if (MODE == 0) {
                int g = n >> 5, j = n & 31;   // pairs never straddle a 32-group
#pragma unroll
                for (int h = 0; h < 2; h++) {
                    float u0 = h ? v2 : v0, u1 = h ? v3 : v1;
                    int r = h ? r1 : r0;
                    __nv_bfloat16 h0 = __float2bfloat16(u0);
                    __nv_bfloat16 h1 = __float2bfloat16(u1);
                    __nv_bfloat16 l0 = __float2bfloat16(u0 - __bfloat162float(h0));
                    __nv_bfloat16 l1 = __float2bfloat16(u1 - __bfloat162float(h1));
                    uint32_t hp = (uint32_t)__bfloat16_as_ushort(h0) |
                                  ((uint32_t)__bfloat16_as_ushort(h1) << 16);
                    uint32_t lp = (uint32_t)__bfloat16_as_ushort(l0) |
                                  ((uint32_t)__bfloat16_as_ushort(l1) << 16);
                    __nv_bfloat16* row = Csplit + (size_t)r * 2 * N + g * 64 + j;
                    *(uint32_t*)row = hp;
                    *(uint32_t*)(row + 32) = lp;
                }
            } else {
                *(float2*)(Cf + (size_t)r0 * N + n) = make_float2(v0, v1);
                *(float2*)(Cf + (size_t)r1 * N + n) = make_float2(v2, v3);
            }
        }
    }
}

// ---------------- K-split 64x64 FFMA2 GEMM partials for final layer ----------
__global__ __launch_bounds__(256, 4)
void gemm64s(const float* __restrict__ A, const float* __restrict__ Bm,
             float* __restrict__ Cp, int N, int K)
{
    __shared__ __align__(16) float As[16 * 64];
    __shared__ __align__(16) float Bs[16 * 64];

    const int tid = threadIdx.x;
    const int split = blockIdx.x;
    const int kbase = split * (K / KSPLIT);
    const int kend = kbase + K / KSPLIT;
    const int m0 = blockIdx.y * 64;
    const int tr = tid >> 4;
    const int tc = tid & 15;
    const int r = tid >> 2;
    const int c0 = (tid & 3) << 2;

    float* C = Cp + (size_t)split * BATCH * OUTP;

    unsigned long long acc[4][2];
#pragma unroll
    for (int i = 0; i < 4; i++) { acc[i][0] = 0ull; acc[i][1] = 0ull; }

    for (int kt = kbase; kt < kend; kt += 16) {
        float4 va = *(const float4*)(A + (size_t)(m0 + r) * K + kt + c0);
        float4 vb = make_float4(0.f, 0.f, 0.f, 0.f);
        if (r < N) vb = *(const float4*)(Bm + (size_t)r * K + kt + c0);

        __syncthreads();
        As[(c0 + 0) * 64 + r] = va.x; As[(c0 + 1) * 64 + r] = va.y;
        As[(c0 + 2) * 64 + r] = va.z; As[(c0 + 3) * 64 + r] = va.w;
        Bs[(c0 + 0) * 64 + r] = vb.x; Bs[(c0 + 1) * 64 + r] = vb.y;
        Bs[(c0 + 2) * 64 + r] = vb.z; Bs[(c0 + 3) * 64 + r] = vb.w;
        __syncthreads();

#pragma unroll
        for (int k = 0; k < 16; k++) {
            float4 a = *(const float4*)&As[k * 64 + tr * 4];
            ulonglong2 bb = *(const ulonglong2*)&Bs[k * 64 + tc * 4];
            unsigned long long b2[2] = {bb.x, bb.y};
            unsigned long long a2[4];
            a2[0] = pack2(a.x, a.x); a2[1] = pack2(a.y, a.y);
            a2[2] = pack2(a.z, a.z); a2[3] = pack2(a.w, a.w);
#pragma unroll
            for (int i = 0; i < 4; i++) {
                ffma2(acc[i][0], a2[i], b2[0]);
                ffma2(acc[i][1], a2[i], b2[1]);
            }
        }
    }

#pragma unroll
    for (int i = 0; i < 4; i++) {
        int mg = m0 + tr * 4 + i;
#pragma unroll
        for (int j = 0; j < 2; j++) {
            int ng = tc * 4 + (j << 1);
            if (ng < N)     C[(size_t)mg * N + ng]     = lo32(acc[i][j]);
            if (ng + 1 < N) C[(size_t)mg * N + ng + 1] = hi32(acc[i][j]);
        }
    }
}

// fixed-order reduction of K-split partials + bias + *100 (deterministic)
__global__ __launch_bounds__(256)
void reduce_par(const float* __restrict__ Cp, const float* __restrict__ bias,
                float* __restrict__ par, int total)
{
    int i = blockIdx.x * blockDim.x + threadIdx.x;
    if (i >= total) return;
    int j = i % OUTP;
    float s = 0.0f;
#pragma unroll
    for (int p = 0; p < KSPLIT; p++)
        s += Cp[(size_t)p * BATCH * OUTP + i];
    par[i] = (s + bias[j]) * 100.0f;
}

// ---------------- DMP Euler integration --------------------------------------
__global__ __launch_bounds__(256)
void dmp_kernel(const float* __restrict__ input, float* __restrict__ out)
{
    __shared__ float xs[NSTEP];
    __shared__ float coef[NSTEP][NBAS];

    const int tid = threadIdx.x;
    if (tid == 0) {
        float x = 1.0f;
        for (int i = 0; i < NSTEP; i++) { x = x - x * 0.01f; xs[i] = x; }
    }
    __syncthreads();
    if (tid < NSTEP) {
        float x = xs[tid];
        float p[NBAS];
        float s = 0.0f;
#pragma unroll
        for (int n = 0; n < NBAS; n++) {
            double cd = exp(-0.25 * (double)n);
            float Cn = (float)cd;
            float Hn = (float)(11.180339887498949 / cd);
            float d = x - Cn;
            p[n] = __expf(-Hn * d * d);
            s += p[n];
        }
        float inv = x / s;
#pragma unroll
        for (int n = 0; n < NBAS; n++) coef[tid][n] = p[n] * inv;
    }
    __syncthreads();

    int r = blockIdx.x * blockDim.x + tid;
    if (r >= BATCH * NDIM) return;
    int b = r / NDIM;
    int d = r - b * NDIM;

    const float* prm = g_par + (size_t)b * OUTP;
    float goal = prm[d];
    float w[NBAS];
#pragma unroll
    for (int n = 0; n < NBAS; n++) w[n] = prm[NDIM + d * NBAS + n];

    float y = input[(size_t)b * D_INPUT + 7 + d];
    float z = input[(size_t)b * D_INPUT + 22 + d];
    float scale = goal - y;
    float prev = y;
    float* o = out + (size_t)r * 10;

#pragma unroll 1
    for (int kk = 0; kk < 10; kk++) {
#pragma unroll
        for (int i = 0; i < 10; i++) {
            int t = kk * 10 + i;
            float fx = scale * (w[0] * coef[t][0] + w[1] * coef[t][1] +
                                w[2] * coef[t][2] + w[3] * coef[t][3] +
                                w[4] * coef[t][4]);
            float dz = 25.0f * (6.25f * (goal - y) - z) + fx;
            y = y + z * 0.01f;
            z = z + dz * 0.01f;
        }
        o[kk] = y - prev;
        prev = y;
    }
}

// ---------------- launch ------------------------------------------------------
extern "C" void kernel_launch(void* const* d_in, const int* in_sizes, int n_in,
                              void* d_out, int out_size)
{
    const float* input = (const float*)d_in[0];
    const float* W0 = (const float*)d_in[1];
    const float* b0 = (const float*)d_in[2];
    const float* W1 = (const float*)d_in[3];
    const float* b1 = (const float*)d_in[4];
    const float* Wl = (const float*)d_in[5];
    const float* bl = (const float*)d_in[6];
    float* out = (float*)d_out;

    static __nv_bfloat16 *in2, *w0_2, *w1_2, *h1_2;
    static float *h2, *parp, *par;
    static bool init_done = false;
    if (!init_done) {
        cudaGetSymbolAddress((void**)&in2, g_in2);
        cudaGetSymbolAddress((void**)&w0_2, g_w0_2);
        cudaGetSymbolAddress((void**)&w1_2, g_w1_2);
        cudaGetSymbolAddress((void**)&h1_2, g_h1_2);
        cudaGetSymbolAddress((void**)&h2, g_h2);
        cudaGetSymbolAddress((void**)&parp, g_parp);
        cudaGetSymbolAddress((void**)&par, g_par);
        cudaFuncSetAttribute(gemm_mma<0>, cudaFuncAttributeMaxDynamicSharedMemorySize, MMA_SMEM);
        cudaFuncSetAttribute(gemm_mma<1>, cudaFuncAttributeMaxDynamicSharedMemorySize, MMA_SMEM);
        init_done = true;
    }

    dim3 blk(256);
    // fp32 -> interleaved [hi|lo] split layouts
    split2<<<(BATCH * D_INPUT / 4 + 255) / 256, blk>>>(input, in2, D_INPUT, BATCH * D_INPUT / 4);
    split2<<<(HIDDEN * D_INPUT / 4 + 255) / 256, blk>>>(W0, w0_2, D_INPUT, HIDDEN * D_INPUT / 4);
    split2<<<(HIDDEN * HIDDEN / 4 + 255) / 256, blk>>>(W1, w1_2, HIDDEN, HIDDEN * HIDDEN / 4);

    // layer 0: tanh(input @ W0^T + b0) -> h1 interleaved (K2 = 256 elems)
    gemm_mma<0><<<dim3(HIDDEN / 128, BATCH / 128), blk, MMA_SMEM>>>(
        in2, w0_2, b0, nullptr, h1_2, HIDDEN, 2 * D_INPUT);
    // layer 1: tanh(h1 @ W1^T + b1) -> fp32 h2 (K2 = 4096 elems, dominant)
    gemm_mma<1><<<dim3(HIDDEN / 128, BATCH / 128), blk, MMA_SMEM>>>(
        h1_2, w1_2, b1, h2, nullptr, HIDDEN, 2 * HIDDEN);
    // final layer, K-split x8 partials, then deterministic reduce
    gemm64s<<<dim3(KSPLIT, BATCH / 64), blk>>>(h2, Wl, parp, OUTP, HIDDEN);
    reduce_par<<<(BATCH * OUTP + 255) / 256, blk>>>(parp, bl, par, BATCH * OUTP);
    // DMP integration + subsample-diff
    dmp_kernel<<<(BATCH * NDIM + 255) / 256, blk>>>(input, out);
}

// round 17
// speedup vs baseline: 1.2309x; 1.0382x over previous
#include <cuda_runtime.h>
#include <cuda_bf16.h>
#include <math.h>
#include <stdint.h>

#define BATCH   16384
#define D_INPUT 128
#define HIDDEN  2048
#define OUTP    54
#define NDIM    9
#define NBAS    5
#define NSTEP   100
#define KSPLIT  8

// ---------------- scratch (device globals: allocation forbidden) -------------
// Interleaved split layout: per 32 orig-K group, 64 bf16 = [hi(32) | lo(32)].
__device__ __nv_bfloat16 g_in2[(size_t)BATCH * 2 * D_INPUT];
__device__ __nv_bfloat16 g_w0_2[(size_t)HIDDEN * 2 * D_INPUT];
__device__ __nv_bfloat16 g_w1_2[(size_t)HIDDEN * 2 * HIDDEN];
__device__ __nv_bfloat16 g_h1_2[(size_t)BATCH * 2 * HIDDEN];
__device__ float g_h2[(size_t)BATCH * HIDDEN];
__device__ float g_parp[KSPLIT][(size_t)BATCH * OUTP];
__device__ float g_par[(size_t)BATCH * OUTP];

// ---------------- helpers -----------------------------------------------------
__device__ __forceinline__ uint32_t smem_u32(const void* p) {
    uint32_t a;
    asm("{ .reg .u64 t; cvta.to.shared.u64 t, %1; cvt.u32.u64 %0, t; }" : "=r"(a) : "l"(p));
    return a;
}
#define SWZ128(off) ((off) ^ (((off) >> 3) & 0x70))

#define CP_ASYNC16(sm, gp) \
    asm volatile("cp.async.cg.shared.global [%0], [%1], 16;" :: "r"(sm), "l"(gp))
#define CP_COMMIT() asm volatile("cp.async.commit_group;" ::: "memory")
#define CP_WAIT(n)  asm volatile("cp.async.wait_group %0;" :: "n"(n) : "memory")

__device__ __forceinline__ void ldm4(uint32_t* r, uint32_t addr) {
    asm volatile("ldmatrix.sync.aligned.m8n8.x4.shared.b16 {%0,%1,%2,%3}, [%4];"
        : "=r"(r[0]), "=r"(r[1]), "=r"(r[2]), "=r"(r[3]) : "r"(addr));
}
__device__ __forceinline__ void mma16816(float* c, const uint32_t* a, const uint32_t* b) {
    asm volatile("mma.sync.aligned.m16n8k16.row.col.f32.bf16.bf16.f32 "
        "{%0,%1,%2,%3}, {%4,%5,%6,%7}, {%8,%9}, {%0,%1,%2,%3};"
        : "+f"(c[0]), "+f"(c[1]), "+f"(c[2]), "+f"(c[3])
        : "r"(a[0]), "r"(a[1]), "r"(a[2]), "r"(a[3]), "r"(b[0]), "r"(b[1]));
}

__device__ __forceinline__ float tanh_acc(float x) {
    float ax = fabsf(x);
    float t;
    if (ax > 9.0f) t = 1.0f;
    else {
        float e = __expf(2.0f * ax);
        t = 1.0f - __fdividef(2.0f, e + 1.0f);
    }
    return copysignf(t, x);
}

__device__ __forceinline__ unsigned long long pack2(float x, float y) {
    unsigned long long r;
    asm("mov.b64 %0, {%1, %2};" : "=l"(r) : "f"(x), "f"(y));
    return r;
}
__device__ __forceinline__ void ffma2(unsigned long long &c, unsigned long long a,
                                      unsigned long long b) {
    asm("fma.rn.f32x2 %0, %1, %2, %0;" : "+l"(c) : "l"(a), "l"(b));
}
__device__ __forceinline__ float lo32(unsigned long long v) { return __uint_as_float((unsigned)v); }
__device__ __forceinline__ float hi32(unsigned long long v) { return __uint_as_float((unsigned)(v >> 32)); }

// ---------------- fp32 -> interleaved [hi32|lo32] bf16 split ------------------
__global__ __launch_bounds__(256)
void split2(const float* __restrict__ src, __nv_bfloat16* __restrict__ dst,
            int K, int n4)
{
    int i = blockIdx.x * blockDim.x + threadIdx.x;
    if (i >= n4) return;
    int K4 = K >> 2;
    int row = i / K4;
    int k = (i - row * K4) << 2;
    int g = k >> 5, j = k & 31;
    float4 v = ((const float4*)src)[i];
    float f[4] = {v.x, v.y, v.z, v.w};
    ushort4 h, l;
    unsigned short* hp = &h.x;
    unsigned short* lp = &l.x;
#pragma unroll
    for (int q = 0; q < 4; q++) {
        __nv_bfloat16 hb = __float2bfloat16(f[q]);
        __nv_bfloat16 lb = __float2bfloat16(f[q] - __bfloat162float(hb));
        hp[q] = __bfloat16_as_ushort(hb);
        lp[q] = __bfloat16_as_ushort(lb);
    }
    __nv_bfloat16* base = dst + (size_t)row * 2 * K + g * 64 + j;
    ((ushort4*)base)[0] = h;
    ((ushort4*)(base + 32))[0] = l;
}

// ---------------- gemm0: 128x128 / 256thr / 3-slot ring (UNCHANGED, proven) ---
#define MMA_STAGE_SZ 32768
#define MMA_B_OFF    16384
#define MMA_SMEM     (3 * MMA_STAGE_SZ)

__device__ __forceinline__ void load_stage_mma(
    uint32_t sb, const __nv_bfloat16* __restrict__ A2,
    const __nv_bfloat16* __restrict__ B2,
    int m0, int n0, int kelem, int K2, int tid)
{
#pragma unroll
    for (int i = 0; i < 4; i++) {
        int id = tid + i * 256;
        int row = id >> 3, c16 = id & 7;
        uint32_t sw = SWZ128((uint32_t)(row * 128 + c16 * 16));
        CP_ASYNC16(sb + sw,             A2 + (size_t)(m0 + row) * K2 + kelem + c16 * 8);
        CP_ASYNC16(sb + MMA_B_OFF + sw, B2 + (size_t)(n0 + row) * K2 + kelem + c16 * 8);
    }
}

template <int MODE>
__global__ __launch_bounds__(256, 2)
void gemm_mma(const __nv_bfloat16* __restrict__ A2, const __nv_bfloat16* __restrict__ B2,
              const float* __restrict__ bias, float* __restrict__ Cf,
              __nv_bfloat16* __restrict__ Csplit, int N, int K2)
{
    extern __shared__ char smem[];
    uint32_t sbase = smem_u32(smem);
    const int tid = threadIdx.x;
    const int wid = tid >> 5, lane = tid & 31;
    const int m0 = blockIdx.y * 128;
    const int n0 = blockIdx.x * 128;
    const int wm = wid >> 2, wn = wid & 3;
    const int nc = K2 / 64;

    uint32_t roA[4], roB[2];
#pragma unroll
    for (int mt = 0; mt < 4; mt++)
        roA[mt] = (uint32_t)((wm * 64 + mt * 16 + (lane & 15)) * 128 + (lane >> 4) * 16);
#pragma unroll
    for (int p = 0; p < 2; p++)
        roB[p] = (uint32_t)((wn * 32 + p * 16 + (lane & 7) + ((lane >> 4) << 3)) * 128 +
                            ((lane >> 3) & 1) * 16);

    float acc[4][4][4];
#pragma unroll
    for (int a = 0; a < 4; a++)
#pragma unroll
        for (int b = 0; b < 4; b++)
#pragma unroll
            for (int q = 0; q < 4; q++) acc[a][b][q] = 0.0f;

    load_stage_mma(sbase, A2, B2, m0, n0, 0, K2, tid);
    CP_COMMIT();
    if (nc > 1) load_stage_mma(sbase + MMA_STAGE_SZ, A2, B2, m0, n0, 64, K2, tid);
    CP_COMMIT();

    for (int c = 0; c < nc; c++) {
        CP_WAIT(1);
        __syncthreads();

        if (c + 2 < nc)
            load_stage_mma(sbase + ((c + 2) % 3) * MMA_STAGE_SZ, A2, B2,
                           m0, n0, (c + 2) * 64, K2, tid);
        CP_COMMIT();

        uint32_t sA = sbase + (c % 3) * MMA_STAGE_SZ;
        uint32_t sB = sA + MMA_B_OFF;

#pragma unroll
        for (int ks = 0; ks < 2; ks++) {
            uint32_t af[4][4], bh[2][4], bl[2][4];
#pragma unroll
            for (int mt = 0; mt < 4; mt++)
                ldm4(af[mt], sA + SWZ128(roA[mt] + ks * 32));
#pragma unroll
            for (int p = 0; p < 2; p++) {
                ldm4(bh[p], sB + SWZ128(roB[p] + ks * 32));
                ldm4(bl[p], sB + SWZ128(roB[p] + 64 + ks * 32));
            }
#pragma unroll
            for (int mt = 0; mt < 4; mt++) {
#pragma unroll
                for (int nt = 0; nt < 4; nt++)
                    mma16816(acc[mt][nt], af[mt], &bh[nt >> 1][(nt & 1) * 2]);
#pragma unroll
                for (int nt = 0; nt < 4; nt++)
                    mma16816(acc[mt][nt], af[mt], &bl[nt >> 1][(nt & 1) * 2]);
                ldm4(af[mt], sA + SWZ128(roA[mt] + 64 + ks * 32));
            }
#pragma unroll
            for (int mt = 0; mt < 4; mt++)
#pragma unroll
                for (int nt = 0; nt < 4; nt++)
                    mma16816(acc[mt][nt], af[mt], &bh[nt >> 1][(nt & 1) * 2]);
        }
    }

    const int mrow = m0 + wm * 64 + (lane >> 2);
    const int nbase = n0 + wn * 32 + 2 * (lane & 3);
#pragma unroll
    for (int mt = 0; mt < 4; mt++) {
#pragma unroll
        for (int nt = 0; nt < 4; nt++) {
            int n = nbase + nt * 8;
            float2 b2 = *(const float2*)(bias + n);
            float v0 = tanh_acc(acc[mt][nt][0] + b2.x);
            float v1 = tanh_acc(acc[mt][nt][1] + b2.y);
            float v2 = tanh_acc(acc[mt][nt][2] + b2.x);
            float v3 = tanh_acc(acc[mt][nt][3] + b2.y);
            int r0 = mrow + mt * 16, r1 = r0 + 8;
            if (MODE == 0) {
                int g = n >> 5, j = n & 31;
#pragma unroll
                for (int h = 0; h < 2; h++) {
                    float u0 = h ? v2 : v0, u1 = h ? v3 : v1;
                    int r = h ? r1 : r0;
                    __nv_bfloat16 h0 = __float2bfloat16(u0);
                    __nv_bfloat16 h1 = __float2bfloat16(u1);
                    __nv_bfloat16 l0 = __float2bfloat16(u0 - __bfloat162float(h0));
                    __nv_bfloat16 l1 = __float2bfloat16(u1 - __bfloat162float(h1));
                    uint32_t hp = (uint32_t)__bfloat16_as_ushort(h0) |
                                  ((uint32_t)__bfloat16_as_ushort(h1) << 16);
                    uint32_t lp = (uint32_t)__bfloat16_as_ushort(l0) |
                                  ((uint32_t)__bfloat16_as_ushort(l1) << 16);
                    __nv_bfloat16* row = Csplit + (size_t)r * 2 * N + g * 64 + j;
                    *(uint32_t*)row = hp;
                    *(uint32_t*)(row + 32) = lp;
                }
            } else {
                *(float2*)(Cf + (size_t)r0 * N + n) = make_float2(v0, v1);
                *(float2*)(Cf + (size_t)r1 * N + n) = make_float2(v2, v3);
            }
        }
    }
}

// ---------------- gemm1: 256x128 / 512thr / 64-K chunks / 2-slot ring ---------
// Same warp-tile (64x32) fragment math; 4x4 warp grid; fp32 output + tanh.
#define G1_SLOT_SZ  98304          // A: 2x32KB groups + B: 2x16KB groups
#define G1_B_OFF    65536
#define G1_SMEM     (2 * G1_SLOT_SZ)   // 192KB

__device__ __forceinline__ void load_stage_g1(
    uint32_t sb, const __nv_bfloat16* __restrict__ A2,
    const __nv_bfloat16* __restrict__ B2,
    int m0, int n0, int kelem, int K2, int tid)
{
#pragma unroll
    for (int g = 0; g < 2; g++) {
        int ke = kelem + g * 64;
        // A: 256 rows x 128B
#pragma unroll
        for (int i = 0; i < 4; i++) {
            int id = tid + i * 512;
            int row = id >> 3, c16 = id & 7;
            uint32_t sw = SWZ128((uint32_t)(row * 128 + c16 * 16));
            CP_ASYNC16(sb + g * 32768 + sw, A2 + (size_t)(m0 + row) * K2 + ke + c16 * 8);
        }
        // B: 128 rows x 128B
#pragma unroll
        for (int i = 0; i < 2; i++) {
            int id = tid + i * 512;
            int row = id >> 3, c16 = id & 7;
            uint32_t sw = SWZ128((uint32_t)(row * 128 + c16 * 16));
            CP_ASYNC16(sb + G1_B_OFF + g * 16384 + sw, B2 + (size_t)(n0 + row) * K2 + ke + c16 * 8);
        }
    }
}

__global__ __launch_bounds__(512, 1)
void gemm_mma256(const __nv_bfloat16* __restrict__ A2, const __nv_bfloat16* __restrict__ B2,
                 const float* __restrict__ bias, float* __restrict__ Cf,
                 int N, int K2)
{
    extern __shared__ char smem[];
    uint32_t sbase = smem_u32(smem);
    const int tid = threadIdx.x;
    const int wid = tid >> 5, lane = tid & 31;
    const int m0 = blockIdx.y * 256;
    const int n0 = blockIdx.x * 128;
    const int wm = wid >> 2, wn = wid & 3;     // 4x4 warp grid
    const int nc = K2 / 128;                   // 64 orig-K (two groups) per chunk

    uint32_t roA[4], roB[2];
#pragma unroll
    for (int mt = 0; mt < 4; mt++)
        roA[mt] = (uint32_t)((wm * 64 + mt * 16 + (lane & 15)) * 128 + (lane >> 4) * 16);
#pragma unroll
    for (int p = 0; p < 2; p++)
        roB[p] = (uint32_t)((wn * 32 + p * 16 + (lane & 7) + ((lane >> 4) << 3)) * 128 +
                            ((lane >> 3) & 1) * 16);

    float acc[4][4][4];
#pragma unroll
    for (int a = 0; a < 4; a++)
#pragma unroll
        for (int b = 0; b < 4; b++)
#pragma unroll
            for (int q = 0; q < 4; q++) acc[a][b][q] = 0.0f;

    load_stage_g1(sbase, A2, B2, m0, n0, 0, K2, tid);
    CP_COMMIT();

    for (int c = 0; c < nc; c++) {
        // slot (c+1)&1 was fully consumed before the trailing barrier of iter c-1
        if (c + 1 < nc)
            load_stage_g1(sbase + ((c + 1) & 1) * G1_SLOT_SZ, A2, B2,
                          m0, n0, (c + 1) * 128, K2, tid);
        CP_COMMIT();
        CP_WAIT(1);           // outstanding {c, c+1} -> chunk c complete
        __syncthreads();      // cross-thread visibility of chunk c

        uint32_t slot = sbase + (c & 1) * G1_SLOT_SZ;
#pragma unroll
        for (int g = 0; g < 2; g++) {
            uint32_t sA = slot + g * 32768;
            uint32_t sB = slot + G1_B_OFF + g * 16384;
#pragma unroll
            for (int ks = 0; ks < 2; ks++) {
                uint32_t af[4][4], bh[2][4], bl[2][4];
#pragma unroll
                for (int mt = 0; mt < 4; mt++)
                    ldm4(af[mt], sA + SWZ128(roA[mt] + ks * 32));
#pragma unroll
                for (int p = 0; p < 2; p++) {
                    ldm4(bh[p], sB + SWZ128(roB[p] + ks * 32));
                    ldm4(bl[p], sB + SWZ128(roB[p] + 64 + ks * 32));
                }
#pragma unroll
                for (int mt = 0; mt < 4; mt++) {
#pragma unroll
                    for (int nt = 0; nt < 4; nt++)
                        mma16816(acc[mt][nt], af[mt], &bh[nt >> 1][(nt & 1) * 2]);
#pragma unroll
                    for (int nt = 0; nt < 4; nt++)
                        mma16816(acc[mt][nt], af[mt], &bl[nt >> 1][(nt & 1) * 2]);
                    ldm4(af[mt], sA + SWZ128(roA[mt] + 64 + ks * 32));
                }
#pragma unroll
                for (int mt = 0; mt < 4; mt++)
#pragma unroll
                    for (int nt = 0; nt < 4; nt++)
                        mma16816(acc[mt][nt], af[mt], &bh[nt >> 1][(nt & 1) * 2]);
            }
        }
        __syncthreads();      // all warps done with slot c before it is overwritten
    }

    const int mrow = m0 + wm * 64 + (lane >> 2);
    const int nbase = n0 + wn * 32 + 2 * (lane & 3);
#pragma unroll
    for (int mt = 0; mt < 4; mt++) {
#pragma unroll
        for (int nt = 0; nt < 4; nt++) {
            int n = nbase + nt * 8;
            float2 b2 = *(const float2*)(bias + n);
            float v0 = tanh_acc(acc[mt][nt][0] + b2.x);
            float v1 = tanh_acc(acc[mt][nt][1] + b2.y);
            float v2 = tanh_acc(acc[mt][nt][2] + b2.x);
            float v3 = tanh_acc(acc[mt][nt][3] + b2.y);
            int r0 = mrow + mt * 16, r1 = r0 + 8;
            *(float2*)(Cf + (size_t)r0 * N + n) = make_float2(v0, v1);
            *(float2*)(Cf + (size_t)r1 * N + n) = make_float2(v2, v3);
        }
    }
}

// ---------------- K-split 64x64 FFMA2 GEMM partials for final layer ----------
__global__ __launch_bounds__(256, 4)
void gemm64s(const float* __restrict__ A, const float* __restrict__ Bm,
             float* __restrict__ Cp, int N, int K)
{
    __shared__ __align__(16) float As[16 * 64];
    __shared__ __align__(16) float Bs[16 * 64];

    const int tid = threadIdx.x;
    const int split = blockIdx.x;
    const int kbase = split * (K / KSPLIT);
    const int kend = kbase + K / KSPLIT;
    const int m0 = blockIdx.y * 64;
    const int tr = tid >> 4;
    const int tc = tid & 15;
    const int r = tid >> 2;
    const int c0 = (tid & 3) << 2;

    float* C = Cp + (size_t)split * BATCH * OUTP;

    unsigned long long acc[4][2];
#pragma unroll
    for (int i = 0; i < 4; i++) { acc[i][0] = 0ull; acc[i][1] = 0ull; }

    for (int kt = kbase; kt < kend; kt += 16) {
        float4 va = *(const float4*)(A + (size_t)(m0 + r) * K + kt + c0);
        float4 vb = make_float4(0.f, 0.f, 0.f, 0.f);
        if (r < N) vb = *(const float4*)(Bm + (size_t)r * K + kt + c0);

        __syncthreads();
        As[(c0 + 0) * 64 + r] = va.x; As[(c0 + 1) * 64 + r] = va.y;
        As[(c0 + 2) * 64 + r] = va.z; As[(c0 + 3) * 64 + r] = va.w;
        Bs[(c0 + 0) * 64 + r] = vb.x; Bs[(c0 + 1) * 64 + r] = vb.y;
        Bs[(c0 + 2) * 64 + r] = vb.z; Bs[(c0 + 3) * 64 + r] = vb.w;
        __syncthreads();

#pragma unroll
        for (int k = 0; k < 16; k++) {
            float4 a = *(const float4*)&As[k * 64 + tr * 4];
            ulonglong2 bb = *(const ulonglong2*)&Bs[k * 64 + tc * 4];
            unsigned long long b2[2] = {bb.x, bb.y};
            unsigned long long a2[4];
            a2[0] = pack2(a.x, a.x); a2[1] = pack2(a.y, a.y);
            a2[2] = pack2(a.z, a.z); a2[3] = pack2(a.w, a.w);
#pragma unroll
            for (int i = 0; i < 4; i++) {
                ffma2(acc[i][0], a2[i], b2[0]);
                ffma2(acc[i][1], a2[i], b2[1]);
            }
        }
    }

#pragma unroll
    for (int i = 0; i < 4; i++) {
        int mg = m0 + tr * 4 + i;
#pragma unroll
        for (int j = 0; j < 2; j++) {
            int ng = tc * 4 + (j << 1);
            if (ng < N)     C[(size_t)mg * N + ng]     = lo32(acc[i][j]);
            if (ng + 1 < N) C[(size_t)mg * N + ng + 1] = hi32(acc[i][j]);
        }
    }
}

// fixed-order reduction of K-split partials + bias + *100 (deterministic)
__global__ __launch_bounds__(256)
void reduce_par(const float* __restrict__ Cp, const float* __restrict__ bias,
                float* __restrict__ par, int total)
{
    int i = blockIdx.x * blockDim.x + threadIdx.x;
    if (i >= total) return;
    int j = i % OUTP;
    float s = 0.0f;
#pragma unroll
    for (int p = 0; p < KSPLIT; p++)
        s += Cp[(size_t)p * BATCH * OUTP + i];
    par[i] = (s + bias[j]) * 100.0f;
}

// ---------------- DMP Euler integration --------------------------------------
__global__ __launch_bounds__(256)
void dmp_kernel(const float* __restrict__ input, float* __restrict__ out)
{
    __shared__ float xs[NSTEP];
    __shared__ float coef[NSTEP][NBAS];

    const int tid = threadIdx.x;
    if (tid == 0) {
        float x = 1.0f;
        for (int i = 0; i < NSTEP; i++) { x = x - x * 0.01f; xs[i] = x; }
    }
    __syncthreads();
    if (tid < NSTEP) {
        float x = xs[tid];
        float p[NBAS];
        float s = 0.0f;
#pragma unroll
        for (int n = 0; n < NBAS; n++) {
            double cd = exp(-0.25 * (double)n);
            float Cn = (float)cd;
            float Hn = (float)(11.180339887498949 / cd);
            float d = x - Cn;
            p[n] = __expf(-Hn * d * d);
            s += p[n];
        }
        float inv = x / s;
#pragma unroll
        for (int n = 0; n < NBAS; n++) coef[tid][n] = p[n] * inv;
    }
    __syncthreads();

    int r = blockIdx.x * blockDim.x + tid;
    if (r >= BATCH * NDIM) return;
    int b = r / NDIM;
    int d = r - b * NDIM;

    const float* prm = g_par + (size_t)b * OUTP;
    float goal = prm[d];
    float w[NBAS];
#pragma unroll
    for (int n = 0; n < NBAS; n++) w[n] = prm[NDIM + d * NBAS + n];

    float y = input[(size_t)b * D_INPUT + 7 + d];
    float z = input[(size_t)b * D_INPUT + 22 + d];
    float scale = goal - y;
    float prev = y;
    float* o = out + (size_t)r * 10;

#pragma unroll 1
    for (int kk = 0; kk < 10; kk++) {
#pragma unroll
        for (int i = 0; i < 10; i++) {
            int t = kk * 10 + i;
            float fx = scale * (w[0] * coef[t][0] + w[1] * coef[t][1] +
                                w[2] * coef[t][2] + w[3] * coef[t][3] +
                                w[4] * coef[t][4]);
            float dz = 25.0f * (6.25f * (goal - y) - z) + fx;
            y = y + z * 0.01f;
            z = z + dz * 0.01f;
        }
        o[kk] = y - prev;
        prev = y;
    }
}

// ---------------- launch ------------------------------------------------------
extern "C" void kernel_launch(void* const* d_in, const int* in_sizes, int n_in,
                              void* d_out, int out_size)
{
    const float* input = (const float*)d_in[0];
    const float* W0 = (const float*)d_in[1];
    const float* b0 = (const float*)d_in[2];
    const float* W1 = (const float*)d_in[3];
    const float* b1 = (const float*)d_in[4];
    const float* Wl = (const float*)d_in[5];
    const float* bl = (const float*)d_in[6];
    float* out = (float*)d_out;

    static __nv_bfloat16 *in2, *w0_2, *w1_2, *h1_2;
    static float *h2, *parp, *par;
    static bool init_done = false;
    if (!init_done) {
        cudaGetSymbolAddress((void**)&in2, g_in2);
        cudaGetSymbolAddress((void**)&w0_2, g_w0_2);
        cudaGetSymbolAddress((void**)&w1_2, g_w1_2);
        cudaGetSymbolAddress((void**)&h1_2, g_h1_2);
        cudaGetSymbolAddress((void**)&h2, g_h2);
        cudaGetSymbolAddress((void**)&parp, g_parp);
        cudaGetSymbolAddress((void**)&par, g_par);
        cudaFuncSetAttribute(gemm_mma<0>, cudaFuncAttributeMaxDynamicSharedMemorySize, MMA_SMEM);
        cudaFuncSetAttribute(gemm_mma256, cudaFuncAttributeMaxDynamicSharedMemorySize, G1_SMEM);
        init_done = true;
    }

    dim3 blk(256);
    // fp32 -> interleaved [hi|lo] split layouts
    split2<<<(BATCH * D_INPUT / 4 + 255) / 256, blk>>>(input, in2, D_INPUT, BATCH * D_INPUT / 4);
    split2<<<(HIDDEN * D_INPUT / 4 + 255) / 256, blk>>>(W0, w0_2, D_INPUT, HIDDEN * D_INPUT / 4);
    split2<<<(HIDDEN * HIDDEN / 4 + 255) / 256, blk>>>(W1, w1_2, HIDDEN, HIDDEN * HIDDEN / 4);

    // layer 0: tanh(input @ W0^T + b0) -> h1 interleaved (K2 = 256 elems)
    gemm_mma<0><<<dim3(HIDDEN / 128, BATCH / 128), blk, MMA_SMEM>>>(
        in2, w0_2, b0, nullptr, h1_2, HIDDEN, 2 * D_INPUT);
    // layer 1: tanh(h1 @ W1^T + b1) -> fp32 h2 (K2 = 4096 elems, dominant)
    gemm_mma256<<<dim3(HIDDEN / 128, BATCH / 256), dim3(512), G1_SMEM>>>(
        h1_2, w1_2, b1, h2, HIDDEN, 2 * HIDDEN);
    // final layer, K-split x8 partials, then deterministic reduce
    gemm64s<<<dim3(KSPLIT, BATCH / 64), blk>>>(h2, Wl, parp, OUTP, HIDDEN);
    reduce_par<<<(BATCH * OUTP + 255) / 256, blk>>>(parp, bl, par, BATCH * OUTP);
    // DMP integration + subsample-diff
    dmp_kernel<<<(BATCH * NDIM + 255) / 256, blk>>>(input, out);
}